// round 17
// baseline (speedup 1.0000x reference)
#include <cuda_runtime.h>
#include <cuda_bf16.h>
#include <cstdint>

#define BATCH 8
#define NSEQ  2048
#define CDIM  512

// ---------------------------------------------------------------------------
// Scratch (__device__ globals per allocation-free rule)
// ---------------------------------------------------------------------------
__device__ __align__(16) __nv_bfloat16 g_fb[BATCH * NSEQ * CDIM];      // feat bf16
__device__ __align__(16) __nv_bfloat16 g_wb[3 * CDIM * CDIM];          // wq,wk,wv bf16
__device__ __align__(16) __nv_bfloat16 g_qb[BATCH * NSEQ * CDIM];
__device__ __align__(16) __nv_bfloat16 g_kb[BATCH * NSEQ * CDIM];
__device__ __align__(16) __nv_bfloat16 g_vb[BATCH * NSEQ * CDIM];      // natural [m][d]
__device__ __align__(16) __nv_bfloat16 g_s[(size_t)BATCH * NSEQ * NSEQ];  // exp(S-30)
// 32 partial sums per row: 16 col-blocks x 2 n-warps.
__device__ __align__(16) float g_spart[BATCH * NSEQ * 32];
// Dependency counters (zeroed by zero_cnt kernel each launch):
//   [CW + z]          : weight matrix z converted      (target 64),  z in 0..2
//   [CF + rb]         : feat rowblock rb converted     (target 16),  rb 0..127
//   [CQ + z*128 + rb] : qkv rowblock rb of matrix z    (target 4),   z in 0..1
//   [CV + bz]         : V CTAs of batch bz             (target 64)
//   [CS + bz]         : scores CTAs of batch bz        (target 256)
#define CW 0
#define CF 8
#define CQ 136
#define CV 392
#define CS 400
#define CNT_N 408
__device__ int g_cnt[CNT_N];

// ---------------------------------------------------------------------------
// Helpers
// ---------------------------------------------------------------------------
__device__ __forceinline__ uint32_t smem_to_u32(const void* p) {
    uint32_t a;
    asm("{ .reg .u64 t; cvta.to.shared.u64 t, %1; cvt.u32.u64 %0, t; }" : "=r"(a) : "l"(p));
    return a;
}

__device__ __forceinline__ void cp_async16(uint32_t saddr, const void* gptr) {
    asm volatile("cp.async.cg.shared.global [%0], [%1], 16;" :: "r"(saddr), "l"(gptr));
}
#define CP_COMMIT() asm volatile("cp.async.commit_group;" ::: "memory")
#define CP_WAIT0()  asm volatile("cp.async.wait_group 0;" ::: "memory")

__device__ __forceinline__ void ldsm4(uint32_t r[4], uint32_t addr) {
    asm volatile("ldmatrix.sync.aligned.m8n8.x4.shared.b16 {%0,%1,%2,%3}, [%4];"
        : "=r"(r[0]), "=r"(r[1]), "=r"(r[2]), "=r"(r[3]) : "r"(addr));
}
__device__ __forceinline__ void ldsm4t(uint32_t r[4], uint32_t addr) {
    asm volatile("ldmatrix.sync.aligned.m8n8.x4.trans.shared.b16 {%0,%1,%2,%3}, [%4];"
        : "=r"(r[0]), "=r"(r[1]), "=r"(r[2]), "=r"(r[3]) : "r"(addr));
}

__device__ __forceinline__ void mma_bf16(float c[4], const uint32_t a[4], const uint32_t b[2]) {
    asm volatile(
        "mma.sync.aligned.m16n8k16.row.col.f32.bf16.bf16.f32 "
        "{%0,%1,%2,%3}, {%4,%5,%6,%7}, {%8,%9}, {%0,%1,%2,%3};"
        : "+f"(c[0]), "+f"(c[1]), "+f"(c[2]), "+f"(c[3])
        : "r"(a[0]), "r"(a[1]), "r"(a[2]), "r"(a[3]), "r"(b[0]), "r"(b[1]));
}

__device__ __forceinline__ uint32_t packbf(float x, float y) {
    __nv_bfloat162 h = __floats2bfloat162_rn(x, y);
    return *reinterpret_cast<uint32_t*>(&h);
}

// ---------------------------------------------------------------------------
// SMEM tile layouts (bf16, padded rows so ldmatrix 16B units hit distinct banks)
//   NT tile: 128 rows x 64 k-bf16, row stride 72 bf16 = 144 B -> 18432 B
//   NN tile:  64 k-rows x 128 n-bf16, row stride 136 bf16 = 272 B -> 17408 B
// ---------------------------------------------------------------------------
#define NT_TILE_B 18432
#define NN_TILE_B 17408

__device__ __forceinline__ void load_ntb(const __nv_bfloat16* __restrict__ g, long ld,
                                         int rowBase, int kt, uint32_t sbase, int tid) {
    #pragma unroll
    for (int i = 0; i < 4; i++) {
        int idx = i * 256 + tid;      // 1024 chunks of 16B
        int r = idx >> 3, f8 = idx & 7;
        cp_async16(sbase + (uint32_t)(r * 144 + f8 * 16),
                   g + (long)(rowBase + r) * ld + kt + f8 * 8);
    }
}

__device__ __forceinline__ void load_nnb(const __nv_bfloat16* __restrict__ g, long ld,
                                         int colBase, int kt, uint32_t sbase, int tid) {
    #pragma unroll
    for (int i = 0; i < 4; i++) {
        int idx = i * 256 + tid;
        int r = idx >> 4, c8 = idx & 15;
        cp_async16(sbase + (uint32_t)(r * 272 + c8 * 16),
                   g + (long)(kt + r) * ld + colBase + c8 * 8);
    }
}

// One 64-k slab, warp tile 32x64. A from NT tile; B NT (BNN=0) or NN+trans (BNN=1).
template<int BNN>
__device__ __forceinline__ void slab_bf16(uint32_t aBase, uint32_t bBase,
                                          float acc[2][8][4], int m0, int n0, int lane) {
    uint32_t aOff[2], bOff[4];
    #pragma unroll
    for (int mt = 0; mt < 2; mt++)
        aOff[mt] = (uint32_t)((m0 + mt * 16 + (lane & 15)) * 144 + ((lane & 16) ? 16 : 0));
    #pragma unroll
    for (int nt2 = 0; nt2 < 4; nt2++) {
        if (BNN)
            bOff[nt2] = (uint32_t)(((lane & 7) + ((lane & 8) ? 8 : 0)) * 272
                        + (n0 + nt2 * 16) * 2 + ((lane & 16) ? 16 : 0));
        else
            bOff[nt2] = (uint32_t)((n0 + nt2 * 16 + (lane & 7) + ((lane & 16) ? 8 : 0)) * 144
                        + ((lane & 8) ? 16 : 0));
    }
    #pragma unroll
    for (int kk = 0; kk < 4; kk++) {
        uint32_t a[2][4];
        ldsm4(a[0], aBase + aOff[0] + kk * 32);
        ldsm4(a[1], aBase + aOff[1] + kk * 32);
        uint32_t b[4][4];
        #pragma unroll
        for (int nt2 = 0; nt2 < 4; nt2++) {
            if (BNN) ldsm4t(b[nt2], bBase + bOff[nt2] + kk * 16 * 272);
            else     ldsm4 (b[nt2], bBase + bOff[nt2] + kk * 32);
        }
        #pragma unroll
        for (int mt = 0; mt < 2; mt++)
            #pragma unroll
            for (int nt2 = 0; nt2 < 4; nt2++) {
                mma_bf16(acc[mt][nt2 * 2 + 0], a[mt], &b[nt2][0]);
                mma_bf16(acc[mt][nt2 * 2 + 1], a[mt], &b[nt2][2]);
            }
    }
}

// ---------------------------------------------------------------------------
// Counter init (must precede mega; 1 CTA).
// ---------------------------------------------------------------------------
__global__ void zero_cnt() {
    if (threadIdx.x < CNT_N) g_cnt[threadIdx.x] = 0;
}

// ---------------------------------------------------------------------------
// Mega kernel roles by bid:
//   [0, 192)            conv weights  (z = bid/64, 1024 f4 per CTA)
//   [192, 2240)         conv feat     (chunk = bid-192, rowblock = chunk/16)
//   [2240, 3776)        qkv           (bid-2240 = rb*12 + z*4 + cb)
//   [3776, 5824)        scores
//   [5824, 6336)        pv
// All dependencies point to strictly lower bids -> guaranteed progress.
// ---------------------------------------------------------------------------
#define CONV_W_CTAS  192
#define CONV_CTAS    2240
#define QKV_CTAS     1536
#define SCORES_CTAS  2048
#define FEAT_F4 (BATCH * NSEQ * CDIM / 4)          // 2097152
#define W_F4    (CDIM * CDIM / 4)                  // 65536

__global__ __launch_bounds__(256, 2) void mega(const float* __restrict__ feat,
                                               float* __restrict__ out,
                                               const float* __restrict__ wq,
                                               const float* __restrict__ wk,
                                               const float* __restrict__ wv,
                                               const float* __restrict__ bq,
                                               const float* __restrict__ bk,
                                               const float* __restrict__ bv)
{
    extern __shared__ char sm[];
    uint32_t sb = smem_to_u32(sm);
    const int tid = threadIdx.x;
    const int wid = tid >> 5, lane = tid & 31;
    const int lq = lane >> 2, lr = lane & 3;
    const int m0 = (wid >> 1) * 32, n0 = (wid & 1) * 64;
    const int bid = blockIdx.x;

    if (bid < CONV_CTAS) {
        // ---------------- conv role (f32 -> bf16), 1024 float4s per CTA ----
        const float4* src;
        uint2* dst;
        long base;
        int cntIdx;
        if (bid < CONV_W_CTAS) {
            int z = bid >> 6;
            src = (const float4*)((z == 0) ? wq : (z == 1) ? wk : wv);
            dst = (uint2*)g_wb + (long)z * W_F4;
            base = (long)(bid & 63) * 1024;
            cntIdx = CW + z;
        } else {
            int chunk = bid - CONV_W_CTAS;
            src = (const float4*)feat;
            dst = (uint2*)g_fb;
            base = (long)chunk * 1024;
            cntIdx = CF + (chunk >> 4);
        }
        #pragma unroll
        for (int i = 0; i < 4; i++) {
            long idx = base + i * 256 + tid;
            float4 v = src[idx];
            uint2 o;
            o.x = packbf(v.x, v.y);
            o.y = packbf(v.z, v.w);
            dst[idx] = o;
        }
        __syncthreads();
        __threadfence();
        if (tid == 0) atomicAdd(&g_cnt[cntIdx], 1);
    } else if (bid < CONV_CTAS + QKV_CTAS) {
        // ---------------- qkv role ----------------
        const int qb = bid - CONV_CTAS;
        const int rb = qb / 12;
        const int rem = qb - rb * 12;
        const int z = rem >> 2;
        const int cb = rem & 3;
        const int rowBase = rb * 128;
        const int colBase = cb * 128;

        // Wait for weight matrix z and feat rowblock rb.
        if (tid == 0) {
            volatile int* wv_ = (volatile int*)&g_cnt[CW + z];
            volatile int* fv  = (volatile int*)&g_cnt[CF + rb];
            while (*wv_ < 64) { }
            while (*fv  < 16) { }
        }
        __syncthreads();

        const __nv_bfloat16* W = g_wb + (long)z * CDIM * CDIM;
        const float* bias = (z == 0) ? bq : (z == 1) ? bk : bv;
        __nv_bfloat16* outM = (z == 0) ? g_qb : (z == 1) ? g_kb : g_vb;

        uint32_t aAddr[2] = { sb, sb + NT_TILE_B };
        uint32_t bAddr[2] = { sb + 2 * NT_TILE_B, sb + 3 * NT_TILE_B };

        float acc[2][8][4] = {};

        load_ntb(g_fb, CDIM, rowBase, 0, aAddr[0], tid);
        load_ntb(W,    CDIM, colBase, 0, bAddr[0], tid);
        CP_COMMIT(); CP_WAIT0();
        __syncthreads();

        const int nslab = CDIM / 64;
        for (int s = 0; s < nslab; s++) {
            int cur = s & 1;
            if (s + 1 < nslab) {
                int nxt = cur ^ 1;
                load_ntb(g_fb, CDIM, rowBase, (s + 1) * 64, aAddr[nxt], tid);
                load_ntb(W,    CDIM, colBase, (s + 1) * 64, bAddr[nxt], tid);
                CP_COMMIT();
            }
            slab_bf16<0>(aAddr[cur], bAddr[cur], acc, m0, n0, lane);
            if (s + 1 < nslab) CP_WAIT0();
            __syncthreads();
        }

        #pragma unroll
        for (int mt = 0; mt < 2; mt++)
            #pragma unroll
            for (int half = 0; half < 2; half++) {
                int row = rowBase + m0 + mt * 16 + lq + half * 8;
                #pragma unroll
                for (int nt = 0; nt < 8; nt++) {
                    int col = colBase + n0 + nt * 8 + lr * 2;
                    uint32_t p = packbf(acc[mt][nt][half * 2 + 0] + bias[col + 0],
                                        acc[mt][nt][half * 2 + 1] + bias[col + 1]);
                    *(uint32_t*)&outM[(long)row * CDIM + col] = p;
                }
            }

        __syncthreads();
        __threadfence();
        if (tid == 0) {
            if (z < 2) atomicAdd(&g_cnt[CQ + z * 128 + rb], 1);
            else       atomicAdd(&g_cnt[CV + (rb >> 4)], 1);
        }
    } else if (bid < CONV_CTAS + QKV_CTAS + SCORES_CTAS) {
        // ---------------- scores role ----------------
        const int sbid = bid - CONV_CTAS - QKV_CTAS;
        const int bz = sbid >> 8;
        const int cib = sbid & 255;
        const int colBase = (cib & 15) * 128;
        const int rowBase = (cib >> 4) * 128;

        if (tid == 0) {
            volatile int* q = (volatile int*)&g_cnt[CQ + 0 * 128 + bz * 16 + (rowBase >> 7)];
            volatile int* k = (volatile int*)&g_cnt[CQ + 1 * 128 + bz * 16 + (colBase >> 7)];
            while (*q < 4) { }
            while (*k < 4) { }
        }
        __syncthreads();

        const __nv_bfloat16* Aq = g_qb + (long)bz * NSEQ * CDIM;
        const __nv_bfloat16* Bk = g_kb + (long)bz * NSEQ * CDIM;
        __nv_bfloat16* outS = g_s + (size_t)bz * NSEQ * NSEQ;

        uint32_t aAddr[2] = { sb, sb + NT_TILE_B };
        uint32_t bAddr[2] = { sb + 2 * NT_TILE_B, sb + 3 * NT_TILE_B };

        float acc[2][8][4] = {};

        load_ntb(Aq, CDIM, rowBase, 0, aAddr[0], tid);
        load_ntb(Bk, CDIM, colBase, 0, bAddr[0], tid);
        CP_COMMIT(); CP_WAIT0();
        __syncthreads();

        const int nslab = CDIM / 64;
        for (int s = 0; s < nslab; s++) {
            int cur = s & 1;
            if (s + 1 < nslab) {
                int nxt = cur ^ 1;
                load_ntb(Aq, CDIM, rowBase, (s + 1) * 64, aAddr[nxt], tid);
                load_ntb(Bk, CDIM, colBase, (s + 1) * 64, bAddr[nxt], tid);
                CP_COMMIT();
            }
            slab_bf16<0>(aAddr[cur], bAddr[cur], acc, m0, n0, lane);
            if (s + 1 < nslab) CP_WAIT0();
            __syncthreads();
        }

        #pragma unroll
        for (int mt = 0; mt < 2; mt++)
            #pragma unroll
            for (int half = 0; half < 2; half++) {
                int row = rowBase + m0 + mt * 16 + lq + half * 8;
                float rp = 0.f;
                #pragma unroll
                for (int nt = 0; nt < 8; nt++) {
                    int col = colBase + n0 + nt * 8 + lr * 2;
                    float e0 = __expf(acc[mt][nt][half * 2 + 0] - 30.0f);
                    float e1 = __expf(acc[mt][nt][half * 2 + 1] - 30.0f);
                    rp += e0 + e1;
                    *(uint32_t*)&outS[(size_t)row * NSEQ + col] = packbf(e0, e1);
                }
                rp += __shfl_xor_sync(0xffffffffu, rp, 1);
                rp += __shfl_xor_sync(0xffffffffu, rp, 2);
                if (lr == 0) {
                    int part = (cib & 15) * 2 + (n0 >> 6);   // 0..31, unique per warp
                    g_spart[((size_t)(bz * NSEQ) + row) * 32 + part] = rp;
                }
            }

        __syncthreads();
        __threadfence();
        if (tid == 0) atomicAdd(&g_cnt[CS + bz], 1);
    } else {
        // ---------------- pv role ----------------
        const int p = bid - CONV_CTAS - QKV_CTAS - SCORES_CTAS;
        const int bz = p >> 6;
        const int cta = p & 63;
        const int colBase = (cta & 3) * 128;
        const int rowBase = (cta >> 2) * 128;

        if (tid == 0) {
            volatile int* sdone = (volatile int*)&g_cnt[CS + bz];
            volatile int* vdone = (volatile int*)&g_cnt[CV + bz];
            while (*vdone < 64) { }
            while (*sdone < 256) { }
        }
        __syncthreads();

        const __nv_bfloat16* Ap = g_s + (size_t)bz * NSEQ * NSEQ;
        const __nv_bfloat16* Bv = g_vb + (long)bz * NSEQ * CDIM;

        uint32_t aAddr[2] = { sb, sb + NT_TILE_B };
        uint32_t bAddr[2] = { sb + 2 * NT_TILE_B, sb + 2 * NT_TILE_B + NN_TILE_B };

        float acc[2][8][4] = {};

        load_ntb(Ap, NSEQ, rowBase, 0, aAddr[0], tid);
        load_nnb(Bv, CDIM, colBase, 0, bAddr[0], tid);
        CP_COMMIT(); CP_WAIT0();
        __syncthreads();

        const int nslab = NSEQ / 64;
        for (int s = 0; s < nslab; s++) {
            int cur = s & 1;
            if (s + 1 < nslab) {
                int nxt = cur ^ 1;
                load_ntb(Ap, NSEQ, rowBase, (s + 1) * 64, aAddr[nxt], tid);
                load_nnb(Bv, CDIM, colBase, (s + 1) * 64, bAddr[nxt], tid);
                CP_COMMIT();
            }
            slab_bf16<1>(aAddr[cur], bAddr[cur], acc, m0, n0, lane);
            if (s + 1 < nslab) CP_WAIT0();
            __syncthreads();
        }

        // Gather row normalizers (L2-coherent loads; written by other SMs).
        float* rsh = (float*)sm;
        if (tid < 128) {
            const float4* pp = (const float4*)(g_spart + ((size_t)(bz * NSEQ) + rowBase + tid) * 32);
            float ssum = 0.f;
            #pragma unroll
            for (int i = 0; i < 8; i++) {
                float4 v = __ldcg(&pp[i]);
                ssum += (v.x + v.y) + (v.z + v.w);
            }
            rsh[tid] = 0.044194173824159216f / ssum;   // (1/sqrt(512)) / rowsum
        }
        __syncthreads();

        #pragma unroll
        for (int mt = 0; mt < 2; mt++)
            #pragma unroll
            for (int half = 0; half < 2; half++) {
                int rloc = m0 + mt * 16 + lq + half * 8;
                long gRow = (long)bz * NSEQ + rowBase + rloc;
                const float nrm = rsh[rloc];
                #pragma unroll
                for (int nt = 0; nt < 8; nt++) {
                    int col = colBase + n0 + nt * 8 + lr * 2;
                    float2 f = *(const float2*)&feat[gRow * CDIM + col];
                    float2 o;
                    o.x = fmaf(acc[mt][nt][half * 2 + 0], nrm, f.x);
                    o.y = fmaf(acc[mt][nt][half * 2 + 1], nrm, f.y);
                    *(float2*)&out[gRow * CDIM + col] = o;
                }
            }
    }
}

// ---------------------------------------------------------------------------
#define SMEM_NT_BYTES (4 * NT_TILE_B)                 // 73728 (max of all roles)

extern "C" void kernel_launch(void* const* d_in, const int* in_sizes, int n_in,
                              void* d_out, int out_size)
{
    const float* feat = (const float*)d_in[0];
    const float* wq   = (const float*)d_in[1];
    const float* bq   = (const float*)d_in[2];
    const float* wk   = (const float*)d_in[3];
    const float* bk   = (const float*)d_in[4];
    const float* wv   = (const float*)d_in[5];
    const float* bv   = (const float*)d_in[6];
    float* out = (float*)d_out;

    cudaFuncSetAttribute(mega, cudaFuncAttributeMaxDynamicSharedMemorySize, SMEM_NT_BYTES);

    // Zero dependency counters (1 CTA), then the fully fused pipeline.
    zero_cnt<<<1, 256>>>();
    mega<<<dim3(CONV_CTAS + QKV_CTAS + SCORES_CTAS + 512), 256, SMEM_NT_BYTES>>>(
        feat, out, wq, wk, wv, bq, bk, bv);
}